// round 17
// baseline (speedup 1.0000x reference)
#include <cuda_runtime.h>
#include <cuda_fp16.h>

#define HH 1024
#define WW 1024
#define NPIX (HH * WW)

// Persistent device-global scratch (no cudaMalloc allowed).
__device__ float4  g_P[NPIX];     // fp32 weights (up,dn,lf,rt); zeros at seeds
__device__ __half2 g_bufAh[NPIX]; // fp16 state ping
__device__ __half2 g_bufBh[NPIX]; // fp16 state pong

__global__ __launch_bounds__(256)
void rw_setup_kernel(const float* __restrict__ img,
                     const int* __restrict__ seeds,
                     __half2* __restrict__ x0)
{
    int j = blockIdx.x * 32 + threadIdx.x;
    int i = blockIdx.y * blockDim.y + threadIdx.y;
    int idx = i * WW + j;

    float c  = img[idx];
    bool  cb = (c > 0.1f);

    const int di[4] = {-1, 1, 0, 0};
    const int dj[4] = { 0, 0,-1, 1};

    float w[4];
    float rowsum = 0.0f;
#pragma unroll
    for (int d = 0; d < 4; d++) {
        int ni = i + di[d], nj = j + dj[d];
        bool valid = (ni >= 0) && (ni < HH) && (nj >= 0) && (nj < WW);
        int nidx = (valid ? ni : i) * WW + (valid ? nj : j);
        float nb = img[nidx];
        float same = ((nb > 0.1f) != cb) ? 1.0f : 0.0f;
        float diff = c - nb + same;
        float wt = valid ? expf(-1.0f - fabsf(diff)) : 0.0f;
        w[d] = wt;
        rowsum += wt;
    }
    float inv = 1.0f / rowsum;

    int s = seeds[idx];
    // Seed rows absorbing: zero weights -> self = 1 exactly.
    float4 p = s ? make_float4(0.f, 0.f, 0.f, 0.f)
                 : make_float4(w[0] * inv, w[1] * inv, w[2] * inv, w[3] * inv);
    g_P[idx] = p;

    // one-hot seed probabilities, exact in fp16 (0 and 1 representable)
    x0[idx] = __floats2half2_rn((s == 1) ? 1.0f : 0.0f,
                                (s == 2) ? 1.0f : 0.0f);
}

// ---------------------------------------------------------------------------
// Four Jacobi steps per launch, tile 32x32, 256 threads, 8 blocks/SM single
// wave. Vertical-pair threads (2 px/thread). State x in fp16 (__half2 packs
// both classes, 4 B/px -> half LDS/STS bytes); P in fp32 float4 (no unpack
// cvts; L2 has headroom). Arithmetic fp32; self = 1 - sum(p) in fp32 keeps
// rows exactly stochastic. Final kernel's last phase writes fp32 to d_out.
//   sA: 38x38 logical origin (by-3, bx-3)   sB: 36x36 origin (by-2, bx-2)
//   p0: global->sA (R=3)  p1: sA->sB (R=2)  p2: sB->sA (R=1)  p3: sA->global
// ---------------------------------------------------------------------------
#define TX 32
#define TY 32
#define SA 38
#define SB 36

__device__ __forceinline__ void store_px(__half2* p, float2 o) {
    *p = __floats2half2_rn(o.x, o.y);
}
__device__ __forceinline__ void store_px(float2* p, float2 o) {
    *p = o;
}

// o = p.x*up + p.y*dn + p.z*lf + p.w*rt + (1-sum(p))*ct, both channels fp32
__device__ __forceinline__
float2 stencil_f(float4 p, float2 up, float2 dn, float2 lf, float2 rt, float2 ct)
{
    float s = 1.0f - ((p.x + p.y) + (p.z + p.w));
    float2 o;
    o.x = p.x*up.x + p.y*dn.x + p.z*lf.x + p.w*rt.x + s*ct.x;
    o.y = p.x*up.y + p.y*dn.y + p.z*lf.y + p.w*rt.y + s*ct.y;
    return o;
}

// One Jacobi sub-step over a DxD output region, 2 vertically-adjacent px per
// thread. in_log/out_log point at logical pixel (by, bx) of their buffers.
//  D: region side (even)  R: region radius  SI/SO: strides
//  GUARD: coords may leave image   GIN: input is global memory
template<int D, int R, int SI, int SO, bool GUARD, bool GIN, typename OutT>
__device__ __forceinline__
void pair_phase(int tid, int by, int bx,
                const __half2* __restrict__ in_log,
                OutT* __restrict__ out_log)
{
    constexpr int TOT   = D * (D / 2);
    constexpr int NITER = (TOT + 255) / 256;
    constexpr bool EXACT = (NITER * 256 == TOT);

#pragma unroll
    for (int it = 0; it < NITER; it++) {
        int e = tid + it * 256;
        if (EXACT || e < TOT) {
            int pr = e / D;
            int cc = e - pr * D;
            int ro = 2 * pr - R;   // logical row of first output px
            int co = cc - R;       // logical col

            // --- P loads first (deep MLP; L2-resident, fp32 LDG.128) ---
            const float4* pp = g_P + (by + ro) * WW + (bx + co);
            float4 p1, p2;
            if (GUARD) {
                bool vc = (unsigned)(bx + co) < WW;
                const float4 z = make_float4(0.f, 0.f, 0.f, 0.f);
                p1 = (vc && (unsigned)(by + ro)     < HH) ? pp[0]  : z;
                p2 = (vc && (unsigned)(by + ro + 1) < HH) ? pp[WW] : z;
            } else {
                p1 = pp[0];
                p2 = pp[WW];
            }

            // --- x reads (fp16): 4-row center column + lf/rt for both rows ---
            const __half2* ip = in_log + ro * SI + co;
            __half2 ha, hb, hc, hd, hl0, hr0, hl1, hr1;
            if (GIN && GUARD) {
                bool vc  = (unsigned)(bx + co)     < WW;
                bool vcl = (unsigned)(bx + co - 1) < WW;
                bool vcr = (unsigned)(bx + co + 1) < WW;
                bool vym = (unsigned)(by + ro - 1) < HH;
                bool vy0 = (unsigned)(by + ro)     < HH;
                bool vy1 = (unsigned)(by + ro + 1) < HH;
                bool vy2 = (unsigned)(by + ro + 2) < HH;
                const __half2 z = __float2half2_rn(0.f);
                ha  = (vym && vc ) ? ip[-SI]     : z;
                hb  = (vy0 && vc ) ? ip[0]       : z;
                hc  = (vy1 && vc ) ? ip[SI]      : z;
                hd  = (vy2 && vc ) ? ip[2 * SI]  : z;
                hl0 = (vy0 && vcl) ? ip[-1]      : z;
                hr0 = (vy0 && vcr) ? ip[1]       : z;
                hl1 = (vy1 && vcl) ? ip[SI - 1]  : z;
                hr1 = (vy1 && vcr) ? ip[SI + 1]  : z;
            } else {
                ha  = ip[-SI];
                hb  = ip[0];
                hc  = ip[SI];
                hd  = ip[2 * SI];
                hl0 = ip[-1];
                hr0 = ip[1];
                hl1 = ip[SI - 1];
                hr1 = ip[SI + 1];
            }

            float2 a   = __half22float2(ha);
            float2 b   = __half22float2(hb);
            float2 c   = __half22float2(hc);
            float2 d   = __half22float2(hd);
            float2 lf0 = __half22float2(hl0);
            float2 rt0 = __half22float2(hr0);
            float2 lf1 = __half22float2(hl1);
            float2 rt1 = __half22float2(hr1);

            float2 o0 = stencil_f(p1, a, c, lf0, rt0, b);
            float2 o1 = stencil_f(p2, b, d, lf1, rt1, c);

            store_px(out_log + ro * SO + co,       o0);
            store_px(out_log + (ro + 1) * SO + co, o1);
        }
    }
}

// LAST: final 4-step kernel -> p3 writes fp32 to d_out
template<bool GUARD, bool LAST>
__device__ __forceinline__
void rw_body(int tid, int by, int bx,
             const __half2* __restrict__ xin,
             __half2* __restrict__ xouth, float2* __restrict__ xoutf,
             __half2* __restrict__ sAl, __half2* __restrict__ sBl)
{
    const __half2* gin = xin + by * WW + bx;

    pair_phase<38, 3, WW, SA, GUARD, true >(tid, by, bx, gin, sAl);   // global -> sA
    __syncthreads();
    pair_phase<36, 2, SA, SB, GUARD, false>(tid, by, bx, sAl, sBl);   // sA -> sB
    __syncthreads();
    pair_phase<34, 1, SB, SA, GUARD, false>(tid, by, bx, sBl, sAl);   // sB -> sA
    __syncthreads();
    // final tile is fully in-image -> never guarded
    if (LAST) {
        pair_phase<32, 0, SA, WW, false, false>(tid, by, bx, sAl,
                                                xoutf + by * WW + bx);
    } else {
        pair_phase<32, 0, SA, WW, false, false>(tid, by, bx, sAl,
                                                xouth + by * WW + bx);
    }
}

template<bool LAST>
__global__ __launch_bounds__(256, 8)
void rw_step4_kernel(const __half2* __restrict__ xin,
                     __half2* __restrict__ xouth,
                     float2* __restrict__ xoutf)
{
    __shared__ __half2 sA[SA * SA];  // 5.8 KB
    __shared__ __half2 sB[SB * SB];  // 5.2 KB

    const int tid = threadIdx.x;
    const int bx  = blockIdx.x * TX;
    const int by  = blockIdx.y * TY;

    __half2* sAl = sA + 3 * SA + 3;  // logical (by, bx)
    __half2* sBl = sB + 2 * SB + 2;

    const bool interior = (bx >= 4) && (bx + 36 <= WW) &&
                          (by >= 4) && (by + 36 <= HH);
    if (interior) rw_body<false, LAST>(tid, by, bx, xin, xouth, xoutf, sAl, sBl);
    else          rw_body<true,  LAST>(tid, by, bx, xin, xouth, xoutf, sAl, sBl);
}

extern "C" void kernel_launch(void* const* d_in, const int* in_sizes, int n_in,
                              void* d_out, int out_size)
{
    const float* img   = (const float*)d_in[0];
    const int*   seeds = (const int*)d_in[1];
    float2*      OUT   = (float2*)d_out;

    __half2 *Ah = nullptr, *Bh = nullptr;
    cudaGetSymbolAddress((void**)&Ah, g_bufAh);
    cudaGetSymbolAddress((void**)&Bh, g_bufBh);

    {
        dim3 blk(32, 8);
        dim3 grd(WW / 32, HH / 8);
        // x0 (fp16) written into Bh; 25 quad-step kernels alternate
        // Bh->Ah->Bh...; t=24 (even, reads Bh) writes fp32 to d_out.
        rw_setup_kernel<<<grd, blk>>>(img, seeds, Bh);
    }

    dim3 blk(256);
    dim3 grd(WW / TX, HH / TY);   // 32 x 32 = 1024 blocks
    for (int t = 0; t < 24; t++) {
        const __half2* xin  = (t & 1) ? Ah : Bh;
        __half2*       xout = (t & 1) ? Bh : Ah;
        rw_step4_kernel<false><<<grd, blk>>>(xin, xout, nullptr);
    }
    // t = 24: reads Bh, writes fp32 result to d_out
    rw_step4_kernel<true><<<grd, blk>>>(Bh, nullptr, OUT);
}